// round 1
// baseline (speedup 1.0000x reference)
#include <cuda_runtime.h>
#include <cstddef>

// Problem constants
#define Bb   64
#define Tt   64
#define QQ   4
#define SS   4
#define DIN  188
#define HH   192
#define NACT 576       // 256 push + 64 pop + 256 repl
#define TILE 256       // Q*S*Q*S
#define GROW (Tt*TILE) // 16384 floats per (b,i) row

// Scratch (no cudaMalloc allowed)
__device__ float g_actions[Bb * NACT];
__device__ float g_tmp[(size_t)Bb * Tt * 64];   // tmp[b,k,u,y,r]
__device__ float g_alphaT[Bb * 16];             // alpha_t[b,r,y]

// ---------------------------------------------------------------------------
// K1: h_new = tanh(xin@W_ih^T + b_ih + h@W_hh^T + b_hh); actions = softmax(...)
// one block per batch, 192 threads
// ---------------------------------------------------------------------------
__global__ void __launch_bounds__(HH) k1_rnn(
    const float* __restrict__ x, const float* __restrict__ h,
    const float* __restrict__ top, const float* __restrict__ Wih,
    const float* __restrict__ bih, const float* __restrict__ Whh,
    const float* __restrict__ bhh, const float* __restrict__ Wlin,
    const float* __restrict__ blin, float* __restrict__ out_h)
{
    const int b = blockIdx.x;
    const int t = threadIdx.x;
    __shared__ float xin[HH], hS[HH], hn[HH], red[HH];

    xin[t] = (t < DIN) ? x[b * DIN + t] : top[b * SS + (t - DIN)];
    hS[t]  = h[b * HH + t];
    if (t < 16) g_alphaT[b * 16 + t] = 0.f;   // zero accumulator for K3
    __syncthreads();

    // h_new[b,t]
    float acc = bih[t] + bhh[t];
    const float* wi = Wih + (size_t)t * HH;
    const float* wh = Whh + (size_t)t * HH;
    #pragma unroll 8
    for (int k = 0; k < HH; k++) acc += xin[k] * wi[k] + hS[k] * wh[k];
    const float hv = tanhf(acc);
    hn[t] = hv;
    out_h[b * HH + t] = hv;
    __syncthreads();

    // logits: 3 per thread (576 total)
    float lv[3];
    float lmax = -1e30f;
    #pragma unroll
    for (int a3 = 0; a3 < 3; a3++) {
        const int a = t * 3 + a3;
        const float* wl = Wlin + (size_t)a * HH;
        float s = blin[a];
        #pragma unroll 8
        for (int k = 0; k < HH; k++) s += hn[k] * wl[k];
        lv[a3] = s;
        lmax = fmaxf(lmax, s);
    }
    // block max reduce (192 -> 64 -> tree)
    red[t] = lmax; __syncthreads();
    if (t < 64) red[t] = fmaxf(red[t], fmaxf(red[t + 64], red[t + 128]));
    __syncthreads();
    for (int o = 32; o > 0; o >>= 1) {
        if (t < o) red[t] = fmaxf(red[t], red[t + o]);
        __syncthreads();
    }
    const float m = red[0];
    __syncthreads();

    float lsum = 0.f;
    #pragma unroll
    for (int a3 = 0; a3 < 3; a3++) { lv[a3] = expf(lv[a3] - m); lsum += lv[a3]; }
    red[t] = lsum; __syncthreads();
    if (t < 64) red[t] = red[t] + red[t + 64] + red[t + 128];
    __syncthreads();
    for (int o = 32; o > 0; o >>= 1) {
        if (t < o) red[t] = red[t] + red[t + o];
        __syncthreads();
    }
    const float inv = 1.f / red[0];
    #pragma unroll
    for (int a3 = 0; a3 < 3; a3++)
        g_actions[b * NACT + t * 3 + a3] = lv[a3] * inv;
}

// ---------------------------------------------------------------------------
// K2: tmp[b,k,u,y,r] = sum_{s,z} gamma[b,k,ts-1,u,y,s,z] * pop[b,s,z,r]
// one block per (b,k), 64 threads
// ---------------------------------------------------------------------------
__global__ void __launch_bounds__(64) k2_tmp(
    const float* __restrict__ gamma, const int* __restrict__ tsp)
{
    const int ts = tsp[0] + 1;
    const int bk = blockIdx.x;            // b*64 + k
    const int b  = bk >> 6;
    const int t  = threadIdx.x;
    __shared__ float gt[TILE], popS[64];

    const float* base = gamma + (((size_t)bk * Tt + (ts - 1)) << 8);
    #pragma unroll
    for (int j = 0; j < 4; j++) gt[t + 64 * j] = base[t + 64 * j];
    popS[t] = g_actions[b * NACT + 256 + t];
    __syncthreads();

    const int u = t >> 4, y = (t >> 2) & 3, r = t & 3;
    float s = 0.f;
    #pragma unroll
    for (int sz = 0; sz < 16; sz++) {
        const int ss = sz >> 2, z = sz & 3;
        s += gt[u * 64 + y * 16 + sz] * popS[ss * 16 + z * 4 + r];
    }
    g_tmp[(size_t)bk * 64 + t] = s;
}

// ---------------------------------------------------------------------------
// K3: fused gamma copy + gamma_t compute + alpha_t accumulation
// one block per (b,i), 256 threads; each thread owns one (q,x,r,y) output elem
// ---------------------------------------------------------------------------
__global__ void __launch_bounds__(TILE) k3_main(
    const float* __restrict__ gamma, const float* __restrict__ alpha,
    const int* __restrict__ tsp, float* __restrict__ out_gamma)
{
    const int ts = tsp[0] + 1;
    const int bi = blockIdx.x;            // b*64 + i
    const int b  = bi >> 6;
    const int i  = bi & 63;
    const int t  = threadIdx.x;

    const size_t row = (size_t)bi << 14;  // * 16384
    const float4* in4  = (const float4*)(gamma + row);
    float4*       out4 = (float4*)(out_gamma + row);

    // Bulk copy of the 64KB row (skip the ts tile — replaced below)
    #pragma unroll
    for (int it = 0; it < 16; it++) {
        const int j = it * 256 + t;       // float4 index; k = j>>6
        if ((j >> 6) != ts) out4[j] = in4[j];
    }

    __shared__ float gcolS[TILE], replS[TILE], red[TILE];
    const float* base = gamma + row;
    gcolS[t] = base[(ts - 1) * TILE + t];            // L1/L2 hit (just copied)
    replS[t] = g_actions[b * NACT + 320 + t];
    __syncthreads();

    const int qx = t >> 4;                // q*4+x
    const int r  = (t >> 2) & 3;
    const int y  = t & 3;

    float acc = 0.f;

    // pop_t: sum over k in (i, ts-2], u in [0,4)
    {
        const float* gp = base + (qx * 16 + y);          // + k*256 + u*4
        const float* tp = g_tmp + ((size_t)b * Tt) * 64 + y * 4 + r;  // + k*64 + u*16
        #pragma unroll 4
        for (int k = i + 1; k <= ts - 2; k++) {
            const float* g  = gp + k * TILE;
            const float* tm = tp + k * 64;
            acc += g[0] * tm[0] + g[4] * tm[16] + g[8] * tm[32] + g[12] * tm[48];
        }
    }

    // repl_t: sum_{s,z} gcol[b,i,q,x,s,z] * repl[b,s,z,r,y]
    {
        const float* gc = gcolS + qx * 16;
        const float* rp = replS + (r * 4 + y);
        #pragma unroll
        for (int sz = 0; sz < 16; sz++) acc += gc[sz] * rp[sz * 16];
    }

    // push_t: only row i == ts-1; push flat index == t
    if (i == ts - 1) acc += g_actions[b * NACT + t];

    out_gamma[row + (size_t)ts * TILE + t] = acc;

    // alpha_t[b,r,y] += alpha[b,i,q,x] * gamma_t
    red[t] = alpha[bi * 16 + qx] * acc;
    __syncthreads();
    if (t < 16) {
        float s = 0.f;
        #pragma unroll
        for (int m2 = 0; m2 < 16; m2++) s += red[t + m2 * 16];
        atomicAdd(&g_alphaT[b * 16 + t], s);
    }
}

// ---------------------------------------------------------------------------
// K4: new_alpha = alpha with [:,ts] = alpha_t; obs = normalized sum over r
// one block per batch, 256 threads
// ---------------------------------------------------------------------------
__global__ void __launch_bounds__(256) k4_final(
    const float* __restrict__ alpha, const int* __restrict__ tsp,
    float* __restrict__ out_alpha, float* __restrict__ out_obs)
{
    const int ts = tsp[0] + 1;
    const int b = blockIdx.x;
    const int t = threadIdx.x;
    const float4* a4 = (const float4*)(alpha + (size_t)b * 1024);
    float4*       o4 = (float4*)(out_alpha + (size_t)b * 1024);
    o4[t] = a4[t];                        // 256 * float4 = 1024 floats
    __syncthreads();
    if (t < 16) out_alpha[(size_t)b * 1024 + ts * 16 + t] = g_alphaT[b * 16 + t];
    if (t == 0) {
        float sy[4] = {0.f, 0.f, 0.f, 0.f};
        float tot = 0.f;
        #pragma unroll
        for (int r = 0; r < 4; r++)
            #pragma unroll
            for (int y = 0; y < 4; y++) {
                const float v = g_alphaT[b * 16 + r * 4 + y];
                sy[y] += v; tot += v;
            }
        const float inv = 1.f / (tot + 1e-5f);
        #pragma unroll
        for (int y = 0; y < 4; y++) out_obs[b * 4 + y] = sy[y] * inv;
    }
}

// ---------------------------------------------------------------------------
extern "C" void kernel_launch(void* const* d_in, const int* in_sizes, int n_in,
                              void* d_out, int out_size)
{
    const float* x     = (const float*)d_in[0];
    const float* h     = (const float*)d_in[1];
    const float* gamma = (const float*)d_in[2];
    const float* alpha = (const float*)d_in[3];
    const float* top   = (const float*)d_in[4];
    const float* Wih   = (const float*)d_in[5];
    const float* bih   = (const float*)d_in[6];
    const float* Whh   = (const float*)d_in[7];
    const float* bhh   = (const float*)d_in[8];
    const float* Wlin  = (const float*)d_in[9];
    const float* blin  = (const float*)d_in[10];
    const int*   tsp   = (const int*)d_in[11];

    float* out = (float*)d_out;
    float* out_h     = out;                                   // 64*192
    float* out_gamma = out + (size_t)Bb * HH;                 // 67,108,864
    float* out_alpha = out_gamma + (size_t)Bb * Tt * Tt * TILE; // 65,536
    float* out_obs   = out_alpha + (size_t)Bb * Tt * 16;      // 256

    k1_rnn<<<Bb, HH>>>(x, h, top, Wih, bih, Whh, bhh, Wlin, blin, out_h);
    k2_tmp<<<Bb * Tt, 64>>>(gamma, tsp);
    k3_main<<<Bb * Tt, TILE>>>(gamma, alpha, tsp, out_gamma);
    k4_final<<<Bb, 256>>>(alpha, tsp, out_alpha, out_obs);
}

// round 6
// speedup vs baseline: 1.0174x; 1.0174x over previous
#include <cuda_runtime.h>
#include <cstddef>

// Problem constants
#define Bb   64
#define Tt   64
#define DIN  188
#define HH   192
#define NACT 576       // 256 push + 64 pop + 256 repl
#define TILE 256       // Q*S*Q*S

// Scratch (no cudaMalloc allowed)
__device__ float g_actions[Bb * NACT];
__device__ float g_tmp[(size_t)Bb * Tt * 64];   // tmp[b,k,u,y,r]  (r contiguous)
__device__ float g_alphaT[Bb * 16];             // alpha_t[b,r,y]

// ---------------------------------------------------------------------------
// K1: RNN cell + softmax(actions); also copies alpha row (independent work)
// one block per batch, 192 threads
// ---------------------------------------------------------------------------
__global__ void __launch_bounds__(HH) k1_rnn(
    const float* __restrict__ x, const float* __restrict__ h,
    const float* __restrict__ top, const float* __restrict__ Wih,
    const float* __restrict__ bih, const float* __restrict__ Whh,
    const float* __restrict__ bhh, const float* __restrict__ Wlin,
    const float* __restrict__ blin, const float* __restrict__ alpha,
    float* __restrict__ out_h, float* __restrict__ out_alpha)
{
    const int b = blockIdx.x;
    const int t = threadIdx.x;
    __shared__ float xin[HH], hS[HH], hn[HH], red[HH];

    // alpha bulk copy (1024 floats = 256 float4); slice ts overwritten in k4
    {
        const float4* a4 = (const float4*)(alpha + (size_t)b * 1024);
        float4*       o4 = (float4*)(out_alpha + (size_t)b * 1024);
        for (int j = t; j < 256; j += HH) o4[j] = a4[j];
    }

    xin[t] = (t < DIN) ? x[b * DIN + t] : top[b * 4 + (t - DIN)];
    hS[t]  = h[b * HH + t];
    if (t < 16) g_alphaT[b * 16 + t] = 0.f;
    __syncthreads();

    float acc = bih[t] + bhh[t];
    const float* wi = Wih + (size_t)t * HH;
    const float* wh = Whh + (size_t)t * HH;
    #pragma unroll 8
    for (int k = 0; k < HH; k++) acc += xin[k] * wi[k] + hS[k] * wh[k];
    const float hv = tanhf(acc);
    hn[t] = hv;
    out_h[b * HH + t] = hv;
    __syncthreads();

    float lv[3];
    float lmax = -1e30f;
    #pragma unroll
    for (int a3 = 0; a3 < 3; a3++) {
        const int a = t * 3 + a3;
        const float* wl = Wlin + (size_t)a * HH;
        float s = blin[a];
        #pragma unroll 8
        for (int k = 0; k < HH; k++) s += hn[k] * wl[k];
        lv[a3] = s;
        lmax = fmaxf(lmax, s);
    }
    red[t] = lmax; __syncthreads();
    if (t < 64) red[t] = fmaxf(red[t], fmaxf(red[t + 64], red[t + 128]));
    __syncthreads();
    for (int o = 32; o > 0; o >>= 1) {
        if (t < o) red[t] = fmaxf(red[t], red[t + o]);
        __syncthreads();
    }
    const float m = red[0];
    __syncthreads();

    float lsum = 0.f;
    #pragma unroll
    for (int a3 = 0; a3 < 3; a3++) { lv[a3] = expf(lv[a3] - m); lsum += lv[a3]; }
    red[t] = lsum; __syncthreads();
    if (t < 64) red[t] = red[t] + red[t + 64] + red[t + 128];
    __syncthreads();
    for (int o = 32; o > 0; o >>= 1) {
        if (t < o) red[t] = red[t] + red[t + o];
        __syncthreads();
    }
    const float inv = 1.f / red[0];
    #pragma unroll
    for (int a3 = 0; a3 < 3; a3++)
        g_actions[b * NACT + t * 3 + a3] = lv[a3] * inv;
}

// ---------------------------------------------------------------------------
// K2: tmp[b,k,u,y,r] = sum_{s,z} gamma[b,k,ts-1,u,y,s,z] * pop[b,s,z,r]
// ---------------------------------------------------------------------------
__global__ void __launch_bounds__(64) k2_tmp(
    const float* __restrict__ gamma, const int* __restrict__ tsp)
{
    const int ts = tsp[0] + 1;
    const int bk = blockIdx.x;            // b*64 + k
    const int b  = bk >> 6;
    const int t  = threadIdx.x;
    __shared__ float gt[TILE], popS[64];

    const float* base = gamma + (((size_t)bk * Tt + (ts - 1)) << 8);
    #pragma unroll
    for (int j = 0; j < 4; j++) gt[t + 64 * j] = base[t + 64 * j];
    popS[t] = g_actions[b * NACT + 256 + t];
    __syncthreads();

    const int u = t >> 4, y = (t >> 2) & 3, r = t & 3;
    float s = 0.f;
    #pragma unroll
    for (int sz = 0; sz < 16; sz++) {
        const int ss = sz >> 2, z = sz & 3;
        s += gt[u * 64 + y * 16 + sz] * popS[ss * 16 + z * 4 + r];
    }
    g_tmp[(size_t)bk * 64 + t] = s;
}

// ---------------------------------------------------------------------------
// K3: fused gamma row copy + gamma_t + alpha_t partials
// one block per (b,i), 256 threads
// thread t -> (qy = t&63 : qx*4+y, kq = t>>6); each computes 4 r-outputs,
// k (and repl's sz) split 4 ways across kq, reduced through smem.
// ---------------------------------------------------------------------------
__global__ void __launch_bounds__(TILE) k3_main(
    const float* __restrict__ gamma, const float* __restrict__ alpha,
    const int* __restrict__ tsp, float* __restrict__ out_gamma)
{
    const int ts = tsp[0] + 1;
    const int bi = blockIdx.x;
    const int b  = bi >> 6;
    const int i  = bi & 63;
    const int t  = threadIdx.x;

    const size_t row = (size_t)bi << 14;  // *16384 floats
    const float4* in4  = (const float4*)(gamma + row);
    float4*       out4 = (float4*)(out_gamma + row);

    __shared__ float4 redS[TILE];         // 4KB
    __shared__ float  gcolS[TILE];
    __shared__ float  replT[TILE];        // repl transposed to [sz][y][r]

    // stage gcol (tile ts-1) + transposed repl while copy loads are in flight
    gcolS[t] = gamma[row + (size_t)(ts - 1) * TILE + t];
    {
        const int sz = t >> 4, y = (t >> 2) & 3, r = t & 3;
        replT[t] = g_actions[b * NACT + 320 + sz * 16 + r * 4 + y];
    }

    // Bulk 64KB row copy, 2 batches of 8 float4 (skip tile k == ts)
    #pragma unroll
    for (int hB = 0; hB < 2; hB++) {
        float4 v[8];
        #pragma unroll
        for (int u2 = 0; u2 < 8; u2++) v[u2] = in4[(hB * 8 + u2) * 256 + t];
        #pragma unroll
        for (int u2 = 0; u2 < 8; u2++) {
            const int j = (hB * 8 + u2) * 256 + t;
            if ((j >> 6) != ts) out4[j] = v[u2];
        }
    }
    __syncthreads();

    const int qy = t & 63;                // qx*4 + y
    const int kq = t >> 6;                // 0..3
    const int qx = qy >> 2;
    const int y  = qy & 3;

    float4 acc = make_float4(0.f, 0.f, 0.f, 0.f);

    // pop_t partial: k = i+1+kq, i+5+kq, ... <= ts-2
    {
        const float*  gk = gamma + row + qx * 16 + y;
        const float*  tb = g_tmp + (size_t)b * (Tt * 64) + y * 4;
        for (int k = i + 1 + kq; k <= ts - 2; k += 4) {
            const float*  g  = gk + k * TILE;
            const float4* tm = (const float4*)(tb + k * 64);
            #pragma unroll
            for (int u = 0; u < 4; u++) {
                const float  gv = g[u * 4];
                const float4 t4 = tm[u * 4];
                acc.x += gv * t4.x; acc.y += gv * t4.y;
                acc.z += gv * t4.z; acc.w += gv * t4.w;
            }
        }
    }

    // repl_t partial: sz = kq*4 .. kq*4+3
    #pragma unroll
    for (int s2 = 0; s2 < 4; s2++) {
        const int   sz = kq * 4 + s2;
        const float gv = gcolS[qx * 16 + sz];
        const float4 t4 = *(const float4*)(replT + sz * 16 + y * 4);
        acc.x += gv * t4.x; acc.y += gv * t4.y;
        acc.z += gv * t4.z; acc.w += gv * t4.w;
    }

    redS[t] = acc;
    __syncthreads();

    if (t < 64) {                          // t == qy
        const float4 a0 = redS[t],       a1 = redS[64 + t];
        const float4 a2 = redS[128 + t], a3 = redS[192 + t];
        float4 s;
        s.x = a0.x + a1.x + a2.x + a3.x;
        s.y = a0.y + a1.y + a2.y + a3.y;
        s.z = a0.z + a1.z + a2.z + a3.z;
        s.w = a0.w + a1.w + a2.w + a3.w;

        if (i == ts - 1) {                 // push_t
            const float* pa = g_actions + b * NACT + qx * 16 + y;
            s.x += pa[0]; s.y += pa[4]; s.z += pa[8]; s.w += pa[12];
        }

        float* o = out_gamma + row + (size_t)ts * TILE + qx * 16 + y;
        o[0] = s.x; o[4] = s.y; o[8] = s.z; o[12] = s.w;

        const float av = alpha[bi * 16 + qx];
        redS[t] = make_float4(av * s.x, av * s.y, av * s.z, av * s.w);
    }
    __syncthreads();

    if (t < 16) {                          // t = r*4 + y
        const int r = t >> 2, yy = t & 3;
        const float* rf = (const float*)redS;
        float s = 0.f;
        #pragma unroll
        for (int q = 0; q < 16; q++) s += rf[(q * 4 + yy) * 4 + r];
        atomicAdd(&g_alphaT[b * 16 + t], s);
    }
}

// ---------------------------------------------------------------------------
// K4: write alpha slice ts + normalized obs
// ---------------------------------------------------------------------------
__global__ void __launch_bounds__(32) k4_final(
    const int* __restrict__ tsp,
    float* __restrict__ out_alpha, float* __restrict__ out_obs)
{
    const int ts = tsp[0] + 1;
    const int b = blockIdx.x;
    const int t = threadIdx.x;
    if (t < 16) out_alpha[(size_t)b * 1024 + ts * 16 + t] = g_alphaT[b * 16 + t];
    if (t == 0) {
        float sy[4] = {0.f, 0.f, 0.f, 0.f};
        float tot = 0.f;
        #pragma unroll
        for (int r = 0; r < 4; r++)
            #pragma unroll
            for (int y = 0; y < 4; y++) {
                const float v = g_alphaT[b * 16 + r * 4 + y];
                sy[y] += v; tot += v;
            }
        const float inv = 1.f / (tot + 1e-5f);
        #pragma unroll
        for (int y = 0; y < 4; y++) out_obs[b * 4 + y] = sy[y] * inv;
    }
}

// ---------------------------------------------------------------------------
extern "C" void kernel_launch(void* const* d_in, const int* in_sizes, int n_in,
                              void* d_out, int out_size)
{
    const float* x     = (const float*)d_in[0];
    const float* h     = (const float*)d_in[1];
    const float* gamma = (const float*)d_in[2];
    const float* alpha = (const float*)d_in[3];
    const float* top   = (const float*)d_in[4];
    const float* Wih   = (const float*)d_in[5];
    const float* bih   = (const float*)d_in[6];
    const float* Whh   = (const float*)d_in[7];
    const float* bhh   = (const float*)d_in[8];
    const float* Wlin  = (const float*)d_in[9];
    const float* blin  = (const float*)d_in[10];
    const int*   tsp   = (const int*)d_in[11];

    float* out = (float*)d_out;
    float* out_h     = out;
    float* out_gamma = out + (size_t)Bb * HH;
    float* out_alpha = out_gamma + (size_t)Bb * Tt * Tt * TILE;
    float* out_obs   = out_alpha + (size_t)Bb * Tt * 16;

    k1_rnn<<<Bb, HH>>>(x, h, top, Wih, bih, Whh, bhh, Wlin, blin,
                       alpha, out_h, out_alpha);
    k2_tmp<<<Bb * Tt, 64>>>(gamma, tsp);
    k3_main<<<Bb * Tt, TILE>>>(gamma, alpha, tsp, out_gamma);
    k4_final<<<Bb, 32>>>(tsp, out_alpha, out_obs);
}

// round 7
// speedup vs baseline: 1.4303x; 1.4059x over previous
#include <cuda_runtime.h>
#include <cstddef>

// Problem constants
#define Bb   64
#define Tt   64
#define DIN  188
#define HH   192
#define NACT 576       // 256 push + 64 pop + 256 repl
#define TILE 256       // Q*S*Q*S

// Scratch (no cudaMalloc allowed)
__device__ float g_actions[Bb * NACT];
__device__ float g_tmp[(size_t)Bb * Tt * 64];   // tmp[b,k,u,y,r]  (r contiguous)
__device__ float g_alphaT[Bb * 16];             // alpha_t[b,r,y]
__device__ unsigned int g_done = 0;             // last-block counter (self-resetting)

// ---------------------------------------------------------------------------
// K1: RNN cell + softmax(actions), COALESCED: warp-per-row GEMV.
// one block per batch, 256 threads (8 warps). Also copies the alpha row.
// ---------------------------------------------------------------------------
__global__ void __launch_bounds__(256) k1_rnn(
    const float* __restrict__ x, const float* __restrict__ h,
    const float* __restrict__ top, const float* __restrict__ Wih,
    const float* __restrict__ bih, const float* __restrict__ Whh,
    const float* __restrict__ bhh, const float* __restrict__ Wlin,
    const float* __restrict__ blin, const float* __restrict__ alpha,
    float* __restrict__ out_h, float* __restrict__ out_alpha)
{
    const int b    = blockIdx.x;
    const int t    = threadIdx.x;
    const int w    = t >> 5;
    const int lane = t & 31;

    __shared__ float xin[HH], hS[HH], hn[HH];
    __shared__ float logits[NACT];
    __shared__ float red[256];

    // alpha bulk copy (1024 floats = 256 float4); slice ts overwritten later
    {
        const float4* a4 = (const float4*)(alpha + (size_t)b * 1024);
        float4*       o4 = (float4*)(out_alpha + (size_t)b * 1024);
        o4[t] = a4[t];
    }

    if (t < HH) {
        xin[t] = (t < DIN) ? x[b * DIN + t] : top[b * 4 + (t - DIN)];
        hS[t]  = h[b * HH + t];
    }
    if (t < 16) g_alphaT[b * 16 + t] = 0.f;
    __syncthreads();

    // h_new: 192 rows, warp w handles rows w, w+8, ..., coalesced across lanes
    #pragma unroll
    for (int j = 0; j < 24; j++) {
        const int r = w + 8 * j;
        const float* wi = Wih + (size_t)r * HH;
        const float* wh = Whh + (size_t)r * HH;
        float acc = 0.f;
        #pragma unroll
        for (int k = lane; k < HH; k += 32)
            acc += xin[k] * wi[k] + hS[k] * wh[k];
        #pragma unroll
        for (int o = 16; o > 0; o >>= 1)
            acc += __shfl_xor_sync(0xffffffffu, acc, o);
        if (lane == 0) {
            const float hv = tanhf(acc + bih[r] + bhh[r]);
            hn[r] = hv;
            out_h[b * HH + r] = hv;
        }
    }
    __syncthreads();

    // logits: 576 rows, warp w handles rows w, w+8, ...
    #pragma unroll
    for (int j = 0; j < 72; j++) {
        const int a = w + 8 * j;
        const float* wl = Wlin + (size_t)a * HH;
        float s = 0.f;
        #pragma unroll
        for (int k = lane; k < HH; k += 32)
            s += hn[k] * wl[k];
        #pragma unroll
        for (int o = 16; o > 0; o >>= 1)
            s += __shfl_xor_sync(0xffffffffu, s, o);
        if (lane == 0) logits[a] = s + blin[a];
    }
    __syncthreads();

    // softmax over 576: thread t owns logits t, t+256, (t<64: t+512)
    float v0 = logits[t];
    float v1 = logits[t + 256];
    float v2 = (t < 64) ? logits[t + 512] : -1e30f;
    float m = fmaxf(v0, fmaxf(v1, v2));
    red[t] = m; __syncthreads();
    for (int o = 128; o > 0; o >>= 1) {
        if (t < o) red[t] = fmaxf(red[t], red[t + o]);
        __syncthreads();
    }
    m = red[0];
    __syncthreads();

    const float e0 = expf(v0 - m);
    const float e1 = expf(v1 - m);
    const float e2 = (t < 64) ? expf(v2 - m) : 0.f;
    red[t] = e0 + e1 + e2; __syncthreads();
    for (int o = 128; o > 0; o >>= 1) {
        if (t < o) red[t] = red[t] + red[t + o];
        __syncthreads();
    }
    const float inv = 1.f / red[0];

    g_actions[b * NACT + t]       = e0 * inv;
    g_actions[b * NACT + t + 256] = e1 * inv;
    if (t < 64) g_actions[b * NACT + t + 512] = e2 * inv;
}

// ---------------------------------------------------------------------------
// K2: tmp[b,k,u,y,r] = sum_{s,z} gamma[b,k,ts-1,u,y,s,z] * pop[b,s,z,r]
// ---------------------------------------------------------------------------
__global__ void __launch_bounds__(64) k2_tmp(
    const float* __restrict__ gamma, const int* __restrict__ tsp)
{
    const int ts = tsp[0] + 1;
    const int bk = blockIdx.x;            // b*64 + k
    const int b  = bk >> 6;
    const int t  = threadIdx.x;
    __shared__ float gt[TILE], popS[64];

    const float* base = gamma + (((size_t)bk * Tt + (ts - 1)) << 8);
    #pragma unroll
    for (int j = 0; j < 4; j++) gt[t + 64 * j] = base[t + 64 * j];
    popS[t] = g_actions[b * NACT + 256 + t];
    __syncthreads();

    const int u = t >> 4, y = (t >> 2) & 3, r = t & 3;
    float s = 0.f;
    #pragma unroll
    for (int sz = 0; sz < 16; sz++) {
        const int ss = sz >> 2, z = sz & 3;
        s += gt[u * 64 + y * 16 + sz] * popS[ss * 16 + z * 4 + r];
    }
    g_tmp[(size_t)bk * 64 + t] = s;
}

// ---------------------------------------------------------------------------
// K3: fused gamma row copy + gamma_t + alpha_t partials.
// Last-finishing block performs the alpha/obs epilogue (formerly k4).
// ---------------------------------------------------------------------------
__global__ void __launch_bounds__(TILE) k3_main(
    const float* __restrict__ gamma, const float* __restrict__ alpha,
    const int* __restrict__ tsp, float* __restrict__ out_gamma,
    float* __restrict__ out_alpha, float* __restrict__ out_obs)
{
    const int ts = tsp[0] + 1;
    const int bi = blockIdx.x;
    const int b  = bi >> 6;
    const int i  = bi & 63;
    const int t  = threadIdx.x;

    const size_t row = (size_t)bi << 14;  // *16384 floats
    const float4* in4  = (const float4*)(gamma + row);
    float4*       out4 = (float4*)(out_gamma + row);

    __shared__ float4 redS[TILE];         // 4KB
    __shared__ float  gcolS[TILE];
    __shared__ float  replT[TILE];        // repl transposed to [sz][y][r]
    __shared__ int    lastFlag;

    // stage gcol (tile ts-1) + transposed repl while copy loads are in flight
    gcolS[t] = gamma[row + (size_t)(ts - 1) * TILE + t];
    {
        const int sz = t >> 4, y = (t >> 2) & 3, r = t & 3;
        replT[t] = g_actions[b * NACT + 320 + sz * 16 + r * 4 + y];
    }

    // Bulk 64KB row copy, 2 batches of 8 float4 (skip tile k == ts)
    #pragma unroll
    for (int hB = 0; hB < 2; hB++) {
        float4 v[8];
        #pragma unroll
        for (int u2 = 0; u2 < 8; u2++) v[u2] = in4[(hB * 8 + u2) * 256 + t];
        #pragma unroll
        for (int u2 = 0; u2 < 8; u2++) {
            const int j = (hB * 8 + u2) * 256 + t;
            if ((j >> 6) != ts) out4[j] = v[u2];
        }
    }
    __syncthreads();

    const int qy = t & 63;                // qx*4 + y
    const int kq = t >> 6;                // 0..3
    const int qx = qy >> 2;
    const int y  = qy & 3;

    float4 acc = make_float4(0.f, 0.f, 0.f, 0.f);

    // pop_t partial: k = i+1+kq, i+5+kq, ... <= ts-2
    {
        const float*  gk = gamma + row + qx * 16 + y;
        const float*  tb = g_tmp + (size_t)b * (Tt * 64) + y * 4;
        for (int k = i + 1 + kq; k <= ts - 2; k += 4) {
            const float*  g  = gk + k * TILE;
            const float4* tm = (const float4*)(tb + k * 64);
            #pragma unroll
            for (int u = 0; u < 4; u++) {
                const float  gv = g[u * 4];
                const float4 t4 = tm[u * 4];
                acc.x += gv * t4.x; acc.y += gv * t4.y;
                acc.z += gv * t4.z; acc.w += gv * t4.w;
            }
        }
    }

    // repl_t partial: sz = kq*4 .. kq*4+3
    #pragma unroll
    for (int s2 = 0; s2 < 4; s2++) {
        const int   sz = kq * 4 + s2;
        const float gv = gcolS[qx * 16 + sz];
        const float4 t4 = *(const float4*)(replT + sz * 16 + y * 4);
        acc.x += gv * t4.x; acc.y += gv * t4.y;
        acc.z += gv * t4.z; acc.w += gv * t4.w;
    }

    redS[t] = acc;
    __syncthreads();

    if (t < 64) {                          // t == qy
        const float4 a0 = redS[t],       a1 = redS[64 + t];
        const float4 a2 = redS[128 + t], a3 = redS[192 + t];
        float4 s;
        s.x = a0.x + a1.x + a2.x + a3.x;
        s.y = a0.y + a1.y + a2.y + a3.y;
        s.z = a0.z + a1.z + a2.z + a3.z;
        s.w = a0.w + a1.w + a2.w + a3.w;

        if (i == ts - 1) {                 // push_t
            const float* pa = g_actions + b * NACT + qx * 16 + y;
            s.x += pa[0]; s.y += pa[4]; s.z += pa[8]; s.w += pa[12];
        }

        float* o = out_gamma + row + (size_t)ts * TILE + qx * 16 + y;
        o[0] = s.x; o[4] = s.y; o[8] = s.z; o[12] = s.w;

        const float av = alpha[bi * 16 + qx];
        redS[t] = make_float4(av * s.x, av * s.y, av * s.z, av * s.w);
    }
    __syncthreads();

    if (t < 16) {                          // t = r*4 + y
        const int r = t >> 2, yy = t & 3;
        const float* rf = (const float*)redS;
        float s = 0.f;
        #pragma unroll
        for (int q = 0; q < 16; q++) s += rf[(q * 4 + yy) * 4 + r];
        atomicAdd(&g_alphaT[b * 16 + t], s);
        __threadfence();                   // order alphaT atomic before counter
    }
    __syncthreads();

    if (t == 0) {
        const unsigned int c = atomicAdd(&g_done, 1u);
        lastFlag = (c == (unsigned int)(gridDim.x - 1)) ? 1 : 0;
    }
    __syncthreads();

    if (lastFlag) {                        // epilogue (formerly k4)
        __threadfence();                   // acquire: see all alphaT atomics
        if (t < 64) {                      // thread t handles batch t
            volatile const float* ga = g_alphaT + t * 16;
            float sy[4] = {0.f, 0.f, 0.f, 0.f};
            float tot = 0.f;
            #pragma unroll
            for (int j = 0; j < 16; j++) {
                const float v = ga[j];
                out_alpha[(size_t)t * 1024 + ts * 16 + j] = v;
                sy[j & 3] += v; tot += v;
            }
            const float inv2 = 1.f / (tot + 1e-5f);
            #pragma unroll
            for (int yy = 0; yy < 4; yy++) out_obs[t * 4 + yy] = sy[yy] * inv2;
        }
        if (t == 0) g_done = 0;            // reset for next graph replay
    }
}

// ---------------------------------------------------------------------------
extern "C" void kernel_launch(void* const* d_in, const int* in_sizes, int n_in,
                              void* d_out, int out_size)
{
    const float* x     = (const float*)d_in[0];
    const float* h     = (const float*)d_in[1];
    const float* gamma = (const float*)d_in[2];
    const float* alpha = (const float*)d_in[3];
    const float* top   = (const float*)d_in[4];
    const float* Wih   = (const float*)d_in[5];
    const float* bih   = (const float*)d_in[6];
    const float* Whh   = (const float*)d_in[7];
    const float* bhh   = (const float*)d_in[8];
    const float* Wlin  = (const float*)d_in[9];
    const float* blin  = (const float*)d_in[10];
    const int*   tsp   = (const int*)d_in[11];

    float* out = (float*)d_out;
    float* out_h     = out;
    float* out_gamma = out + (size_t)Bb * HH;
    float* out_alpha = out_gamma + (size_t)Bb * Tt * Tt * TILE;
    float* out_obs   = out_alpha + (size_t)Bb * Tt * 16;

    k1_rnn<<<Bb, 256>>>(x, h, top, Wih, bih, Whh, bhh, Wlin, blin,
                        alpha, out_h, out_alpha);
    k2_tmp<<<Bb * Tt, 64>>>(gamma, tsp);
    k3_main<<<Bb * Tt, TILE>>>(gamma, alpha, tsp, out_gamma,
                               out_alpha, out_obs);
}